// round 5
// baseline (speedup 1.0000x reference)
#include <cuda_runtime.h>
#include <math.h>
#include <stdint.h>

#define N 2048
#define H 64
#define DIN 128

__device__ float g_dA[N];
__device__ float g_h[N*H];
__device__ float g_hn[N*H];
__device__ float g_hd[N*H];
__device__ float g_hsq[N];
__device__ int   g_idx[N*4];
__device__ float g_cval[N*4];
__device__ float g_dc[N];
__device__ float g_Z1s[N*2*H];
__device__ float g_Z1f[N*2*H];
__device__ float g_part[4*N*2*H];
__device__ float g_zf[N*H], g_zt[N*H], g_zcf[N*H], g_zct[N*H];
__device__ float g_Lcf[N*H], g_Lct[N*H];
__device__ float g_cs[2*H];
__device__ double g_G[128*128];
__device__ double g_M1[64*64];
__device__ double g_M2[64*64];

__device__ __forceinline__ float leaky_f(float v){ return v > 0.f ? v : 0.1f*v; }

__device__ __forceinline__ unsigned int fmap(float v){
  unsigned int u = __float_as_uint(v);
  return (u & 0x80000000u) ? ~u : (u | 0x80000000u);
}

__device__ __forceinline__ void top4_insert(unsigned long long* t, unsigned long long key){
  if (key > t[3]) {
    t[3] = key;
    unsigned long long tmp;
    if (t[3] > t[2]) { tmp = t[2]; t[2] = t[3]; t[3] = tmp; }
    if (t[2] > t[1]) { tmp = t[1]; t[1] = t[2]; t[2] = tmp; }
    if (t[1] > t[0]) { tmp = t[0]; t[0] = t[1]; t[1] = tmp; }
  }
}

__global__ __launch_bounds__(256) void k_rowsum(const float* __restrict__ A){
  int i = blockIdx.x;
  float s = 0.f;
  for (int j = threadIdx.x; j < N; j += 256) s += A[(size_t)i*N + j];
  __shared__ float sh[256];
  sh[threadIdx.x] = s; __syncthreads();
  for (int o = 128; o > 0; o >>= 1){
    if (threadIdx.x < o) sh[threadIdx.x] += sh[threadIdx.x + o];
    __syncthreads();
  }
  if (threadIdx.x == 0) g_dA[i] = rsqrtf(sh[0] + 1e-10f);
}

__global__ __launch_bounds__(256) void k_h(const float* __restrict__ x,
                                           const float* __restrict__ W1,
                                           const float* __restrict__ b1){
  __shared__ float Ws[64][129];
  __shared__ float xs[16][128];
  __shared__ float hs[16][65];
  __shared__ float ss[16];
  int tid = threadIdx.x;
  int base = blockIdx.x * 16;
  for (int e = tid; e < 64*128; e += 256) Ws[e>>7][e&127] = W1[e];
  for (int e = tid; e < 16*128; e += 256) xs[e>>7][e&127] = x[(size_t)base*128 + e];
  __syncthreads();
  int o = tid & 63, rg = tid >> 6;
  float hv[4];
  #pragma unroll
  for (int rr = 0; rr < 4; rr++){
    int rl = rg*4 + rr;
    float a = b1[o];
    #pragma unroll 16
    for (int d = 0; d < 128; d++) a = fmaf(Ws[o][d], xs[rl][d], a);
    hv[rr] = leaky_f(a);
    hs[rl][o] = hv[rr];
  }
  __syncthreads();
  if (tid < 16){
    float s = 0.f;
    #pragma unroll 8
    for (int d = 0; d < 64; d++) s = fmaf(hs[tid][d], hs[tid][d], s);
    ss[tid] = s;
    g_hsq[base + tid] = s;
  }
  __syncthreads();
  #pragma unroll
  for (int rr = 0; rr < 4; rr++){
    int rl = rg*4 + rr, row = base + rl;
    float rn = rsqrtf(ss[rl]);
    float v = hv[rr];
    g_h [row*64 + o] = v;
    g_hn[row*64 + o] = v*rn + 1e-10f;
    g_hd[row*64 + o] = v*g_dA[row];
  }
}

__global__ __launch_bounds__(256) void k_heat(){
  __shared__ __align__(16) float Bs[64][68];
  __shared__ float bsq[64];
  __shared__ unsigned long long cand[16][64];
  int tid = threadIdx.x;
  int r = tid >> 4;
  int c = tid & 15;
  int ibase = blockIdx.x * 16;
  int row = ibase + r;
  float4 hi[16];
  #pragma unroll
  for (int d4 = 0; d4 < 16; d4++)
    hi[d4] = *(const float4*)&g_h[row*64 + d4*4];
  float asq = g_hsq[row];
  unsigned long long t[4] = {0ull,0ull,0ull,0ull};
  for (int jc = 0; jc < N; jc += 64){
    __syncthreads();
    for (int e = tid; e < 64*64; e += 256)
      Bs[e>>6][e&63] = g_h[(jc + (e>>6))*64 + (e&63)];
    if (tid < 64) bsq[tid] = g_hsq[jc + tid];
    __syncthreads();
    #pragma unroll
    for (int q = 0; q < 4; q++){
      int jl = c + q*16;
      const float4* bp = (const float4*)&Bs[jl][0];
      float a = 0.f;
      #pragma unroll
      for (int d4 = 0; d4 < 16; d4++){
        float4 b = bp[d4];
        a = fmaf(hi[d4].x, b.x, a); a = fmaf(hi[d4].y, b.y, a);
        a = fmaf(hi[d4].z, b.z, a); a = fmaf(hi[d4].w, b.w, a);
      }
      float dist = asq + bsq[jl] - 2.f*a + 6.4e-9f;
      int j = jc + jl;
      unsigned long long key = ((unsigned long long)fmap(-dist) << 32)
                             | (unsigned int)(2047 - j);
      top4_insert(t, key);
    }
  }
  #pragma unroll
  for (int q = 0; q < 4; q++) cand[r][c*4 + q] = t[q];
  __syncthreads();
  if (tid < 16){
    unsigned long long m[4] = {0ull,0ull,0ull,0ull};
    for (int e = 0; e < 64; e++) top4_insert(m, cand[tid][e]);
    #pragma unroll
    for (int q = 0; q < 4; q++)
      g_idx[(ibase + tid)*4 + q] = 2047 - (int)(unsigned int)(m[q] & 0xFFFFFFFFull);
  }
}

__global__ __launch_bounds__(256) void k_cos(){
  int w = threadIdx.x >> 5;
  int lane = threadIdx.x & 31;
  int row = blockIdx.x * 8 + w;
  float c[4];
  #pragma unroll
  for (int t = 0; t < 4; t++){
    int j = g_idx[row*4 + t];
    float s = g_hn[row*64 + lane]      * g_hn[j*64 + lane]
            + g_hn[row*64 + 32 + lane] * g_hn[j*64 + 32 + lane];
    for (int o = 16; o > 0; o >>= 1) s += __shfl_down_sync(0xffffffffu, s, o);
    c[t] = s;
  }
  if (lane == 0){
    float rs = c[0] + c[1] + c[2] + c[3];
    g_dc[row] = rsqrtf(rs + 1e-10f);
    #pragma unroll
    for (int t = 0; t < 4; t++) g_cval[row*4 + t] = c[t];
  }
}

template<int C>
__global__ __launch_bounds__(256) void k_gemmA(const float* __restrict__ A){
  constexpr int RT = 4096 / C;
  constexpr int CG = C / 8;
  __shared__ __align__(16) float As[RT][65];
  __shared__ __align__(16) float Bs[64][C + 4];
  const float* __restrict__ B = (C == 64) ? (const float*)g_hd : (const float*)g_Z1s;
  int tid = threadIdx.x;
  int rowbase = blockIdx.x * RT;
  int s = blockIdx.y;
  int kb0 = s * 512;
  int colg = tid % CG, rowg = tid / CG;
  int r0 = rowg*2, c0 = colg*8;
  float acc[2][8];
  #pragma unroll
  for (int rr = 0; rr < 2; rr++)
    #pragma unroll
    for (int cc = 0; cc < 8; cc++) acc[rr][cc] = 0.f;
  for (int kb = kb0; kb < kb0 + 512; kb += 64){
    __syncthreads();
    for (int e = tid; e < RT*64; e += 256)
      As[e>>6][e&63] = A[(size_t)(rowbase + (e>>6))*N + kb + (e&63)];
    for (int e = tid; e < 64*C; e += 256){
      int kk = e / C, cc = e % C;
      Bs[kk][cc] = B[(kb + kk)*C + cc];
    }
    __syncthreads();
    #pragma unroll 16
    for (int kk = 0; kk < 64; kk++){
      float a0 = As[r0][kk], a1 = As[r0+1][kk];
      float4 b0 = *(const float4*)&Bs[kk][c0];
      float4 b1 = *(const float4*)&Bs[kk][c0 + 4];
      acc[0][0] = fmaf(a0, b0.x, acc[0][0]); acc[0][1] = fmaf(a0, b0.y, acc[0][1]);
      acc[0][2] = fmaf(a0, b0.z, acc[0][2]); acc[0][3] = fmaf(a0, b0.w, acc[0][3]);
      acc[0][4] = fmaf(a0, b1.x, acc[0][4]); acc[0][5] = fmaf(a0, b1.y, acc[0][5]);
      acc[0][6] = fmaf(a0, b1.z, acc[0][6]); acc[0][7] = fmaf(a0, b1.w, acc[0][7]);
      acc[1][0] = fmaf(a1, b0.x, acc[1][0]); acc[1][1] = fmaf(a1, b0.y, acc[1][1]);
      acc[1][2] = fmaf(a1, b0.z, acc[1][2]); acc[1][3] = fmaf(a1, b0.w, acc[1][3]);
      acc[1][4] = fmaf(a1, b1.x, acc[1][4]); acc[1][5] = fmaf(a1, b1.y, acc[1][5]);
      acc[1][6] = fmaf(a1, b1.z, acc[1][6]); acc[1][7] = fmaf(a1, b1.w, acc[1][7]);
    }
  }
  float* dst = g_part + (size_t)s*N*C;
  #pragma unroll
  for (int rr = 0; rr < 2; rr++)
    #pragma unroll
    for (int cc = 0; cc < 8; cc++)
      dst[(rowbase + r0 + rr)*C + c0 + cc] = acc[rr][cc];
}

__global__ __launch_bounds__(256) void k_z1t(const float* __restrict__ WT1, const float* __restrict__ bT1,
                                             const float* __restrict__ WC1, const float* __restrict__ bC1){
  __shared__ float Wa_[64][65], Wb_[64][65];
  __shared__ float ps[4][65];
  int tid = threadIdx.x; int sub = tid >> 6; int o = tid & 63;
  for (int e = tid; e < 64*64; e += 256){
    Wa_[e>>6][e&63] = WT1[e];
    Wb_[e>>6][e&63] = WC1[e];
  }
  int row = blockIdx.x*4 + sub;
  float p = g_part[row*64+o] + g_part[N*64 + row*64+o]
          + g_part[2*N*64 + row*64+o] + g_part[3*N*64 + row*64+o];
  float da = g_dA[row];
  ps[sub][o] = da * p;
  __syncthreads();
  float a1 = bT1[o], a2 = bC1[o];
  #pragma unroll 16
  for (int d = 0; d < 64; d++){
    float m = ps[sub][d];
    a1 = fmaf(Wa_[o][d], m, a1);
    a2 = fmaf(Wb_[o][d], m, a2);
  }
  g_Z1s[row*128 + o]      = da * leaky_f(a1);
  g_Z1s[row*128 + 64 + o] = da * leaky_f(a2);
}

__global__ __launch_bounds__(256) void k_z2t(const float* __restrict__ WT2, const float* __restrict__ bT2,
                                             const float* __restrict__ WC2, const float* __restrict__ bC2){
  __shared__ float Wa_[64][65], Wb_[64][65];
  __shared__ float ps[4][130];
  __shared__ float red[4][64];
  int tid = threadIdx.x; int sub = tid >> 6; int o = tid & 63;
  for (int e = tid; e < 64*64; e += 256){
    Wa_[e>>6][e&63] = WT2[e];
    Wb_[e>>6][e&63] = WC2[e];
  }
  int row = blockIdx.x*4 + sub;
  float da = g_dA[row];
  float pA = g_part[row*128+o] + g_part[N*128 + row*128+o]
           + g_part[2*N*128 + row*128+o] + g_part[3*N*128 + row*128+o];
  float pB = g_part[row*128+64+o] + g_part[N*128 + row*128+64+o]
           + g_part[2*N*128 + row*128+64+o] + g_part[3*N*128 + row*128+64+o];
  ps[sub][o]      = da * pA;
  ps[sub][64 + o] = da * pB;
  __syncthreads();
  float a1 = bT2[o], a2 = bC2[o];
  #pragma unroll 16
  for (int d = 0; d < 64; d++){
    a1 = fmaf(Wa_[o][d], ps[sub][d],      a1);
    a2 = fmaf(Wb_[o][d], ps[sub][64 + d], a2);
  }
  float zt  = leaky_f(a1);
  float zct = leaky_f(a2);
  g_zt [row*64 + o] = zt;
  g_zct[row*64 + o] = zct;
  red[sub][o] = zct*zct;
  __syncthreads();
  for (int off = 32; off > 0; off >>= 1){
    if (o < off) red[sub][o] += red[sub][o + off];
    __syncthreads();
  }
  float mn = sqrtf(red[sub][0] * 0.015625f) + 1e-10f;
  g_Lct[row*64 + o] = zct / mn;
}

__global__ __launch_bounds__(256) void k_z1f(const float* __restrict__ WF1, const float* __restrict__ bF1,
                                             const float* __restrict__ WC1, const float* __restrict__ bC1){
  __shared__ float Wa_[64][65], Wb_[64][65];
  __shared__ float ms[4][65];
  int tid = threadIdx.x; int sub = tid >> 6; int o = tid & 63;
  for (int e = tid; e < 64*64; e += 256){
    Wa_[e>>6][e&63] = WF1[e];
    Wb_[e>>6][e&63] = WC1[e];
  }
  int row = blockIdx.x*4 + sub;
  float dci = g_dc[row];
  float m = 0.f;
  #pragma unroll
  for (int t = 0; t < 4; t++){
    int j = g_idx[row*4 + t];
    float coef = g_cval[row*4 + t] * dci * g_dc[j];
    m = fmaf(coef, g_h[j*64 + o], m);
  }
  ms[sub][o] = m;
  __syncthreads();
  float a1 = bF1[o], a2 = bC1[o];
  #pragma unroll 16
  for (int d = 0; d < 64; d++){
    float v = ms[sub][d];
    a1 = fmaf(Wa_[o][d], v, a1);
    a2 = fmaf(Wb_[o][d], v, a2);
  }
  g_Z1f[row*128 + o]      = leaky_f(a1);
  g_Z1f[row*128 + 64 + o] = leaky_f(a2);
}

__global__ __launch_bounds__(256) void k_z2f(const float* __restrict__ WF2, const float* __restrict__ bF2,
                                             const float* __restrict__ WC2, const float* __restrict__ bC2){
  __shared__ float Wa_[64][65], Wb_[64][65];
  __shared__ float ms[4][130];
  __shared__ float red[4][64];
  int tid = threadIdx.x; int sub = tid >> 6; int o = tid & 63;
  for (int e = tid; e < 64*64; e += 256){
    Wa_[e>>6][e&63] = WF2[e];
    Wb_[e>>6][e&63] = WC2[e];
  }
  int row = blockIdx.x*4 + sub;
  float dci = g_dc[row];
  float mf = 0.f, mc = 0.f;
  #pragma unroll
  for (int t = 0; t < 4; t++){
    int j = g_idx[row*4 + t];
    float coef = g_cval[row*4 + t] * dci * g_dc[j];
    mf = fmaf(coef, g_Z1f[j*128 + o],      mf);
    mc = fmaf(coef, g_Z1f[j*128 + 64 + o], mc);
  }
  ms[sub][o]      = mf;
  ms[sub][64 + o] = mc;
  __syncthreads();
  float a1 = bF2[o], a2 = bC2[o];
  #pragma unroll 16
  for (int d = 0; d < 64; d++){
    a1 = fmaf(Wa_[o][d], ms[sub][d],      a1);
    a2 = fmaf(Wb_[o][d], ms[sub][64 + d], a2);
  }
  float zf  = leaky_f(a1);
  float zcf = leaky_f(a2);
  g_zf [row*64 + o] = zf;
  g_zcf[row*64 + o] = zcf;
  red[sub][o] = zcf*zcf;
  __syncthreads();
  for (int off = 32; off > 0; off >>= 1){
    if (o < off) red[sub][o] += red[sub][o + off];
    __syncthreads();
  }
  float mn = sqrtf(red[sub][0] * 0.015625f) + 1e-10f;
  g_Lcf[row*64 + o] = zcf / mn;
}

__global__ __launch_bounds__(256) void k_colmean(){
  int b = blockIdx.x;
  const float* src = (b < 64) ? g_zt : g_zf;
  int col = b & 63;
  float s = 0.f;
  for (int i = threadIdx.x; i < N; i += 256) s += src[i*64 + col];
  __shared__ float sh[256];
  sh[threadIdx.x] = s; __syncthreads();
  for (int o = 128; o > 0; o >>= 1){
    if (threadIdx.x < o) sh[threadIdx.x] += sh[threadIdx.x + o];
    __syncthreads();
  }
  if (threadIdx.x == 0) g_cs[b] = sh[0] / (float)N;
}

__global__ __launch_bounds__(256) void k_gram(int mode){
  const float *A0, *A1, *B0, *B1, *mean; double* out; int cb;
  if (mode == 0){ A0 = g_Lcf; A1 = g_Lct; B0 = g_Lcf; B1 = g_Lct; mean = 0; out = g_G; cb = 128; }
  else if (mode == 1){ A0 = g_zt; A1 = 0; B0 = g_zct; B1 = 0; mean = g_cs;      out = g_M1; cb = 64; }
  else              { A0 = g_zf; A1 = 0; B0 = g_zcf; B1 = 0; mean = g_cs + 64; out = g_M2; cb = 64; }
  int ci0 = blockIdx.x * 16, cj0 = blockIdx.y * 16;
  const float* Ap = (ci0 < 64) ? A0 : A1; int ca_off = ci0 & 63;
  const float* Bp = (cj0 < 64) ? B0 : B1; int cb_off = cj0 & 63;
  __shared__ float As[16][17], Bs[16][17];
  int tid = threadIdx.x;
  int ty = tid >> 4, tx = tid & 15;
  double acc = 0.0; float f = 0.f;
  for (int n0 = 0; n0 < N; n0 += 16){
    __syncthreads();
    int r = n0 + ty;
    float av = Ap[r*64 + ca_off + tx];
    if (mean) av -= mean[ca_off + tx];
    As[ty][tx] = av;
    Bs[ty][tx] = Bp[r*64 + cb_off + tx];
    __syncthreads();
    #pragma unroll
    for (int r2 = 0; r2 < 16; r2++) f = fmaf(As[r2][ty], Bs[r2][tx], f);
    if (((n0 >> 4) & 7) == 7){ acc += (double)f; f = 0.f; }
  }
  out[(ci0 + ty)*cb + cj0 + tx] = acc;
}

__global__ __launch_bounds__(256) void k_att(const float* __restrict__ Wa, const float* __restrict__ ba,
                                             const float* __restrict__ q,  const float* __restrict__ W2,
                                             const float* __restrict__ b2, float* __restrict__ out){
  __shared__ float Was[64][65];
  __shared__ float qv[64];
  __shared__ float zsh[4][3][64];
  __shared__ float red[4][64];
  __shared__ float sv[4][3];
  __shared__ float av[4][3];
  __shared__ float zag[4][64];
  int tid = threadIdx.x; int sub = tid >> 6; int o = tid & 63;
  for (int e = tid; e < 64*64; e += 256) Was[e>>6][e&63] = Wa[e];
  if (tid < 64) qv[tid] = q[tid];
  __syncthreads();
  int row = blockIdx.x*4 + sub;
  float zfv  = g_zf [row*64 + o];
  float ztv  = g_zt [row*64 + o];
  float zcv  = 0.5f*(g_zcf[row*64 + o] + g_zct[row*64 + o]);
  zsh[sub][0][o] = zfv;
  zsh[sub][1][o] = ztv;
  zsh[sub][2][o] = zcv;
  __syncthreads();
  #pragma unroll
  for (int kk = 0; kk < 3; kk++){
    float t = ba[o];
    #pragma unroll 16
    for (int d = 0; d < 64; d++) t = fmaf(Was[o][d], zsh[sub][kk][d], t);
    t = tanhf(t) * qv[o];
    red[sub][o] = t;
    __syncthreads();
    if (o < 32) red[sub][o] += red[sub][o + 32];
    __syncthreads();
    if (o < 32){
      float s = red[sub][o];
      for (int off = 16; off > 0; off >>= 1) s += __shfl_down_sync(0xffffffffu, s, off);
      if (o == 0) sv[sub][kk] = s;
    }
    __syncthreads();
  }
  if (o == 0){
    float m = fmaxf(sv[sub][0], fmaxf(sv[sub][1], sv[sub][2]));
    float e0 = expf(sv[sub][0]-m), e1 = expf(sv[sub][1]-m), e2 = expf(sv[sub][2]-m);
    float inv = 1.f/(e0+e1+e2);
    av[sub][0] = e0*inv; av[sub][1] = e1*inv; av[sub][2] = e2*inv;
  }
  __syncthreads();
  zag[sub][o] = av[sub][0]*zfv + av[sub][1]*ztv + av[sub][2]*zcv;
  __syncthreads();
  if (o < 7){
    float v = b2[o];
    #pragma unroll 16
    for (int d = 0; d < 64; d++) v = fmaf(W2[o*64 + d], zag[sub][d], v);
    out[row*7 + o] = v;
  }
}

__global__ __launch_bounds__(256) void k_final(float* __restrict__ out){
  int tid = threadIdx.x;
  double lc = 0.0, ld = 0.0;
  for (int e = tid; e < 128*128; e += 256){
    int a = e >> 7, b = e & 127;
    double s = ((a < 64) == (b < 64)) ? 1.0 : -1.0;
    double g = g_G[e];
    lc += s * g * g;
  }
  for (int e = tid; e < 64*64; e += 256){
    double m1 = g_M1[e]; ld += m1*m1;
    double m2 = g_M2[e]; ld += m2*m2;
  }
  __shared__ double s1[256], s2[256];
  s1[tid] = lc; s2[tid] = ld; __syncthreads();
  for (int o = 128; o > 0; o >>= 1){
    if (tid < o){ s1[tid] += s1[tid + o]; s2[tid] += s2[tid + o]; }
    __syncthreads();
  }
  if (tid == 0){
    out[N*7]     = (float)(s1[0] / ((double)N * (double)N));
    out[N*7 + 1] = (float)(s2[0] / (2047.0 * 2047.0));
  }
}

extern "C" void kernel_launch(void* const* d_in, const int* in_sizes, int n_in,
                              void* d_out, int out_size){
  const float* x   = (const float*)d_in[0];
  const float* A   = (const float*)d_in[1];
  const float* W1  = (const float*)d_in[3];
  const float* b1  = (const float*)d_in[4];
  const float* WF1 = (const float*)d_in[5];
  const float* bF1 = (const float*)d_in[6];
  const float* WF2 = (const float*)d_in[7];
  const float* bF2 = (const float*)d_in[8];
  const float* WT1 = (const float*)d_in[9];
  const float* bT1 = (const float*)d_in[10];
  const float* WT2 = (const float*)d_in[11];
  const float* bT2 = (const float*)d_in[12];
  const float* WC1 = (const float*)d_in[13];
  const float* bC1 = (const float*)d_in[14];
  const float* WC2 = (const float*)d_in[15];
  const float* bC2 = (const float*)d_in[16];
  const float* Wa  = (const float*)d_in[17];
  const float* ba  = (const float*)d_in[18];
  const float* q   = (const float*)d_in[19];
  const float* W2  = (const float*)d_in[20];
  const float* b2  = (const float*)d_in[21];
  float* out = (float*)d_out;

  k_rowsum<<<N, 256>>>(A);
  k_h<<<N/16, 256>>>(x, W1, b1);
  k_heat<<<N/16, 256>>>();
  k_cos<<<N/8, 256>>>();
  k_gemmA<64><<<dim3(32, 4), 256>>>(A);
  k_z1t<<<N/4, 256>>>(WT1, bT1, WC1, bC1);
  k_gemmA<128><<<dim3(64, 4), 256>>>(A);
  k_z2t<<<N/4, 256>>>(WT2, bT2, WC2, bC2);
  k_z1f<<<N/4, 256>>>(WF1, bF1, WC1, bC1);
  k_z2f<<<N/4, 256>>>(WF2, bF2, WC2, bC2);
  k_colmean<<<128, 256>>>();
  k_gram<<<dim3(8, 8), 256>>>(0);
  k_gram<<<dim3(4, 4), 256>>>(1);
  k_gram<<<dim3(4, 4), 256>>>(2);
  k_att<<<N/4, 256>>>(Wa, ba, q, W2, b2, out);
  k_final<<<1, 256>>>(out);
}